// round 3
// baseline (speedup 1.0000x reference)
#include <cuda_runtime.h>
#include <cuda_bf16.h>
#include <math.h>

typedef unsigned int uint;

#define VOCAB 32000
#define HDIM  1024
#define EHDIM 1024
#define NB    32
#define LSEQ  128
#define XDIM  2048
#define G3H   3072
#define NROW  (NB*LSEQ)
#define GRID  148

// ---------------- scratch ----------------
__device__ float g_Uk[NB*LSEQ*HDIM];
__device__ float g_h0[NB*HDIM];
__device__ float g_h1[NB*HDIM];
__device__ float g_q[NB*XDIM];
__device__ float g_Wq[NB*HDIM];
__device__ float g_scores[NB*LSEQ];
__device__ float g_x[NB*XDIM];
__device__ float g_gh0[NB*G3H];
__device__ float g_gh1[NB*G3H];
__device__ float g_gi0[NB*G3H];
__device__ float g_gi1[NB*G3H];
__device__ __nv_bfloat162 g_fcw2[VOCAB*HDIM/2];
__device__ __nv_bfloat162 g_A2[NROW*HDIM/2];
__device__ unsigned g_bar;
__device__ unsigned g_gen;

// ---------------- grid barrier ----------------
__device__ __forceinline__ void gsync(int nb) {
    __syncthreads();
    if (threadIdx.x == 0) {
        volatile unsigned* vg = &g_gen;
        unsigned gen = *vg;
        __threadfence();
        unsigned old = atomicInc(&g_bar, (unsigned)(nb - 1));
        if (old == (unsigned)(nb - 1)) {
            __threadfence();
            *vg = gen + 1;
        } else {
            while (*vg == gen) __nanosleep(64);
            __threadfence();
        }
    }
    __syncthreads();
}

__device__ __forceinline__ float wsum(float v) {
#pragma unroll
    for (int o = 16; o > 0; o >>= 1) v += __shfl_xor_sync(0xffffffffu, v, o);
    return v;
}
__device__ __forceinline__ float wmaxr(float v) {
#pragma unroll
    for (int o = 16; o > 0; o >>= 1) v = fmaxf(v, __shfl_xor_sync(0xffffffffu, v, o));
    return v;
}
__device__ __forceinline__ float sigmoidf(float x) { return 1.f / (1.f + expf(-x)); }

// ---------------- block-tiled GEMM: C[32 x JT] = A[32 x K] @ W[JT x K]^T + b ----------------
// SMEM staged in 64-k chunks; A read once per tile.
template <int JT>
__device__ __forceinline__ void gemm_tile(const float* __restrict__ A, int K,
                                          const float* __restrict__ W,
                                          const float* __restrict__ bias,
                                          float* __restrict__ C, int ldc, int jbase,
                                          float* sA, float* sW) {
    const int tid = threadIdx.x;
    constexpr int MT = JT / 32;          // rows per thread (JT64->2, JT32->1)
    constexpr int SWS = JT + 4;          // sW row stride (floats), 16B aligned
    const int jq = tid % (JT / 4);       // j-quad
    const int mg = tid / (JT / 4);       // m group
    float acc[MT][4];
#pragma unroll
    for (int r = 0; r < MT; r++)
#pragma unroll
        for (int u = 0; u < 4; u++) acc[r][u] = 0.f;

    for (int k0 = 0; k0 < K; k0 += 64) {
        // stage A chunk 32x64 (transposed: sA[k][m], stride 34)
#pragma unroll
        for (int i = 0; i < 2; i++) {
            int idx = tid + i * 256;
            int m = idx >> 4, kq = (idx & 15) * 4;
            float4 v = *(const float4*)(A + m * K + k0 + kq);
            sA[(kq + 0) * 34 + m] = v.x;
            sA[(kq + 1) * 34 + m] = v.y;
            sA[(kq + 2) * 34 + m] = v.z;
            sA[(kq + 3) * 34 + m] = v.w;
        }
        // stage W chunk JTx64 (transposed: sW[k][j])
#pragma unroll
        for (int i = 0; i < JT / 16; i++) {
            int idx = tid + i * 256;
            int j = idx >> 4, kq = (idx & 15) * 4;
            float4 v = *(const float4*)(W + (size_t)(jbase + j) * K + k0 + kq);
            sW[(kq + 0) * SWS + j] = v.x;
            sW[(kq + 1) * SWS + j] = v.y;
            sW[(kq + 2) * SWS + j] = v.z;
            sW[(kq + 3) * SWS + j] = v.w;
        }
        __syncthreads();
#pragma unroll
        for (int k = 0; k < 64; k++) {
            float4 w = *(const float4*)&sW[k * SWS + jq * 4];
            if (MT == 2) {
                float2 a = *(const float2*)&sA[k * 34 + mg * 2];
                acc[0][0] += a.x * w.x; acc[0][1] += a.x * w.y;
                acc[0][2] += a.x * w.z; acc[0][3] += a.x * w.w;
                acc[1][0] += a.y * w.x; acc[1][1] += a.y * w.y;
                acc[1][2] += a.y * w.z; acc[1][3] += a.y * w.w;
            } else {
                float a = sA[k * 34 + mg];
                acc[0][0] += a * w.x; acc[0][1] += a * w.y;
                acc[0][2] += a * w.z; acc[0][3] += a * w.w;
            }
        }
        __syncthreads();
    }
#pragma unroll
    for (int r = 0; r < MT; r++) {
        int m = mg * MT + r;
#pragma unroll
        for (int u = 0; u < 4; u++) {
            int j = jbase + jq * 4 + u;
            C[(size_t)m * ldc + j] = acc[r][u] + bias[j];
        }
    }
}

// ---------------- persistent megakernel: the 128-step recurrence ----------------
__global__ void __launch_bounds__(256, 1) k_mega(
    const float* __restrict__ enc, const int* __restrict__ tgt,
    const float* __restrict__ emb,
    const float* __restrict__ Wa_w, const float* __restrict__ Wa_b,
    const float* __restrict__ Va_w, const float* __restrict__ Va_b,
    const float* __restrict__ Wih0, const float* __restrict__ Whh0,
    const float* __restrict__ bih0, const float* __restrict__ bhh0,
    const float* __restrict__ Wih1, const float* __restrict__ Whh1,
    const float* __restrict__ bih1, const float* __restrict__ bhh1,
    float* __restrict__ att) {
    __shared__ float s_mem[64 * 34 + 64 * 68];
    float* sA = s_mem;
    float* sW = s_mem + 64 * 34;

    const int nbk = gridDim.x;
    const int tid = threadIdx.x;
    const int wid = tid >> 5, lane = tid & 31;
    const int gw = blockIdx.x * 8 + wid;
    const int NW = nbk * 8;
    const int gt = blockIdx.x * 256 + tid;
    const int NT = nbk * 256;
    const float Vab = Va_b[0];

    for (int step = 0; step < LSEQ; step++) {
        // ---- P1: Wq = q@Wa^T (32 tiles JT32), gh0 = h0@Whh0^T, gh1 = h1@Whh1^T (48+48 JT64)
        for (int t = blockIdx.x; t < 128; t += nbk) {
            if (t < 32)
                gemm_tile<32>(g_q, XDIM, Wa_w, Wa_b, g_Wq, HDIM, t * 32, sA, sW);
            else if (t < 80)
                gemm_tile<64>(g_h0, HDIM, Whh0, bhh0, g_gh0, G3H, (t - 32) * 64, sA, sW);
            else
                gemm_tile<64>(g_h1, HDIM, Whh1, bhh1, g_gh1, G3H, (t - 80) * 64, sA, sW);
        }
        gsync(nbk);

        // ---- P2a: scores[n][l] = Va . tanh(Wq[n] + Uk[n][l]) + Vab
        for (int t = gw; t < NB * LSEQ; t += NW) {
            int n = t >> 7;
            const float* uk = g_Uk + (size_t)t * HDIM;
            const float* wq = g_Wq + n * HDIM;
            float s = 0.f;
#pragma unroll 4
            for (int h = lane; h < HDIM; h += 32)
                s += Va_w[h] * tanhf(wq[h] + uk[h]);
            s = wsum(s);
            if (lane == 0) g_scores[t] = s + Vab;
        }
        gsync(nbk);

        // ---- P2c: softmax (per-warp redundant) + context + embedding -> g_x, att out
        for (int t = gw; t < 2048; t += NW) {
            if (t < 1024) {
                int n = t >> 5, c = t & 31, d = c * 32 + lane;
                const float* sc = g_scores + n * LSEQ;
                float e[4];
                float m0 = fmaxf(fmaxf(sc[lane * 4 + 0], sc[lane * 4 + 1]),
                                 fmaxf(sc[lane * 4 + 2], sc[lane * 4 + 3]));
                float mx = wmaxr(m0);
                float lsum = 0.f;
#pragma unroll
                for (int i = 0; i < 4; i++) { e[i] = expf(sc[lane * 4 + i] - mx); lsum += e[i]; }
                float inv = 1.f / wsum(lsum);
                if (c == 0) {
                    float* ap = att + ((size_t)n * LSEQ + step) * LSEQ + lane * 4;
#pragma unroll
                    for (int i = 0; i < 4; i++) ap[i] = e[i] * inv;
                }
                float ctx = 0.f;
                const float* ep = enc + (size_t)n * EHDIM + d;
#pragma unroll 4
                for (int l = 0; l < LSEQ; l++) {
                    float wl = __shfl_sync(0xffffffffu, e[l & 3], l >> 2);
                    ctx += wl * ep[(size_t)l * (NB * EHDIM)];
                }
                g_x[n * XDIM + d] = ctx * inv;
            } else {
                int u = t - 1024;
                int n = u >> 5, c = u & 31, j = c * 32 + lane;
                int tok = tgt[n * LSEQ + step];
                g_x[n * XDIM + EHDIM + j] = emb[(size_t)tok * HDIM + j];
            }
        }
        gsync(nbk);

        // ---- P3: gi0 = x@Wih0^T (96 tiles JT32, K=2048)
        for (int t = blockIdx.x; t < 96; t += nbk)
            gemm_tile<32>(g_x, XDIM, Wih0, bih0, g_gi0, G3H, t * 32, sA, sW);
        gsync(nbk);

        // ---- comb0 -> h0, q[:,0:1024]
        for (int i = gt; i < NB * HDIM; i += NT) {
            int n = i >> 10, j = i & 1023;
            const float* gi = g_gi0 + n * G3H;
            const float* gh = g_gh0 + n * G3H;
            float r = sigmoidf(gi[j] + gh[j]);
            float z = sigmoidf(gi[HDIM + j] + gh[HDIM + j]);
            float nn = tanhf(gi[2 * HDIM + j] + r * gh[2 * HDIM + j]);
            float h = (1.f - z) * nn + z * g_h0[i];
            g_h0[i] = h;
            g_q[n * XDIM + j] = h;
        }
        gsync(nbk);

        // ---- P4: gi1 = h0@Wih1^T (96 tiles JT32, K=1024)
        for (int t = blockIdx.x; t < 96; t += nbk)
            gemm_tile<32>(g_h0, HDIM, Wih1, bih1, g_gi1, G3H, t * 32, sA, sW);
        gsync(nbk);

        // ---- comb1 -> h1, q[:,1024:2048], A2 (bf16 history)
        for (int i = gt; i < NB * HDIM; i += NT) {
            int n = i >> 10, j = i & 1023;
            const float* gi = g_gi1 + n * G3H;
            const float* gh = g_gh1 + n * G3H;
            float r = sigmoidf(gi[j] + gh[j]);
            float z = sigmoidf(gi[HDIM + j] + gh[HDIM + j]);
            float nn = tanhf(gi[2 * HDIM + j] + r * gh[2 * HDIM + j]);
            float h = (1.f - z) * nn + z * g_h1[i];
            g_h1[i] = h;
            g_q[n * XDIM + HDIM + j] = h;
            ((__nv_bfloat16*)g_A2)[(size_t)(step * NB + n) * HDIM + j] = __float2bfloat16(h);
        }
        gsync(nbk);
    }
}

// ---------------- init ----------------
__global__ void k_zero() {
    int i = blockIdx.x * 256 + threadIdx.x;
    if (i == 0) { g_bar = 0; g_gen = 0; }
    if (i < NB * HDIM) { g_h0[i] = 0.f; g_h1[i] = 0.f; }
    if (i < NB * XDIM) { g_q[i] = 0.f; }
}

__global__ void k_cvt_fcw(const float* __restrict__ w) {
    int stride = gridDim.x * blockDim.x;
    for (int i = blockIdx.x * blockDim.x + threadIdx.x; i < VOCAB * HDIM / 2; i += stride) {
        float2 f = ((const float2*)w)[i];
        g_fcw2[i] = __floats2bfloat162_rn(f.x, f.y);
    }
}

// ---------------- Uk = keys @ Ua_w^T + Ua_b ----------------
__global__ void k_uk(const float* __restrict__ enc, const float* __restrict__ Uw,
                     const float* __restrict__ Ub) {
    __shared__ float As[16][68];
    __shared__ float Bs[16][68];
    int bm = blockIdx.y, bn = blockIdx.x;
    int tid = threadIdx.x;
    int tm = (tid >> 4) << 2;
    int tn = (tid & 15) << 2;
    float acc[4][4];
#pragma unroll
    for (int i = 0; i < 4; i++)
#pragma unroll
        for (int j = 0; j < 4; j++) acc[i][j] = 0.f;

    int lm = tid >> 2;
    int lk = (tid & 3) << 2;
    int r = bm * 64 + lm;
    int nb = r >> 7;
    int lb = r & 127;
    const float* Arow = enc + ((size_t)lb * NB + nb) * EHDIM;
    const float* Brow = Uw + (size_t)(bn * 64 + lm) * EHDIM;

    for (int k0 = 0; k0 < EHDIM; k0 += 16) {
        float4 av = *(const float4*)(Arow + k0 + lk);
        float4 bv = *(const float4*)(Brow + k0 + lk);
        As[lk + 0][lm] = av.x; As[lk + 1][lm] = av.y; As[lk + 2][lm] = av.z; As[lk + 3][lm] = av.w;
        Bs[lk + 0][lm] = bv.x; Bs[lk + 1][lm] = bv.y; Bs[lk + 2][lm] = bv.z; Bs[lk + 3][lm] = bv.w;
        __syncthreads();
#pragma unroll
        for (int kk = 0; kk < 16; kk++) {
            float a[4], b[4];
#pragma unroll
            for (int i = 0; i < 4; i++) { a[i] = As[kk][tm + i]; b[i] = Bs[kk][tn + i]; }
#pragma unroll
            for (int i = 0; i < 4; i++)
#pragma unroll
                for (int j = 0; j < 4; j++) acc[i][j] += a[i] * b[j];
        }
        __syncthreads();
    }
#pragma unroll
    for (int i = 0; i < 4; i++) {
        int rr = bm * 64 + tm + i;
#pragma unroll
        for (int j = 0; j < 4; j++) {
            int c = bn * 64 + tn + j;
            g_Uk[(size_t)rr * HDIM + c] = acc[i][j] + Ub[c];
        }
    }
}

// ---------------- FC (bf16 mma) + log_softmax ----------------
__device__ __forceinline__ void mma_bf16(float* c, uint a0, uint a1, uint a2, uint a3,
                                         uint b0, uint b1) {
    asm volatile(
        "mma.sync.aligned.m16n8k16.row.col.f32.bf16.bf16.f32 "
        "{%0,%1,%2,%3}, {%4,%5,%6,%7}, {%8,%9}, {%0,%1,%2,%3};\n"
        : "+f"(c[0]), "+f"(c[1]), "+f"(c[2]), "+f"(c[3])
        : "r"(a0), "r"(a1), "r"(a2), "r"(a3), "r"(b0), "r"(b1));
}

__global__ void __launch_bounds__(256) k_fc(const float* __restrict__ fcb, float* __restrict__ out) {
    __shared__ __nv_bfloat16 As[64][18];
    __shared__ __nv_bfloat16 Bs[64][18];
    int bm = blockIdx.y, bn = blockIdx.x;
    int tid = threadIdx.x, wid = tid >> 5, lane = tid & 31;
    int g = lane >> 2, tg = lane & 3;
    int warpM = wid >> 2, warpN = wid & 3;
    float acc[2][2][4];
#pragma unroll
    for (int a = 0; a < 2; a++)
#pragma unroll
        for (int b = 0; b < 2; b++)
#pragma unroll
            for (int c = 0; c < 4; c++) acc[a][b][c] = 0.f;

    const uint* Ag = (const uint*)g_A2;
    const uint* Bg = (const uint*)g_fcw2;

    for (int kt = 0; kt < 64; kt++) {
#pragma unroll
        for (int i = 0; i < 2; i++) {
            int idx = tid + i * 256;
            int m = idx >> 3, p = idx & 7;
            *(uint*)&As[m][p * 2] = Ag[(size_t)(bm * 64 + m) * 512 + kt * 8 + p];
            *(uint*)&Bs[m][p * 2] = Bg[(size_t)(bn * 64 + m) * 512 + kt * 8 + p];
        }
        __syncthreads();
#pragma unroll
        for (int mt = 0; mt < 2; mt++) {
            int m0 = warpM * 32 + mt * 16;
            uint a0 = *(const uint*)&As[m0 + g][tg * 2];
            uint a1 = *(const uint*)&As[m0 + g + 8][tg * 2];
            uint a2 = *(const uint*)&As[m0 + g][8 + tg * 2];
            uint a3 = *(const uint*)&As[m0 + g + 8][8 + tg * 2];
#pragma unroll
            for (int nt = 0; nt < 2; nt++) {
                int n0 = warpN * 16 + nt * 8;
                uint b0 = *(const uint*)&Bs[n0 + g][tg * 2];
                uint b1 = *(const uint*)&Bs[n0 + g][8 + tg * 2];
                mma_bf16(acc[mt][nt], a0, a1, a2, a3, b0, b1);
            }
        }
        __syncthreads();
    }
#pragma unroll
    for (int mt = 0; mt < 2; mt++) {
#pragma unroll
        for (int nt = 0; nt < 2; nt++) {
            int r0 = bm * 64 + warpM * 32 + mt * 16 + g;
            int c = bn * 64 + warpN * 16 + nt * 8 + tg * 2;
            float bv0 = fcb[c], bv1 = fcb[c + 1];
            {
                int l = r0 >> 5, n = r0 & 31;
                float* p = out + ((size_t)(n * LSEQ + l)) * VOCAB + c;
                p[0] = acc[mt][nt][0] + bv0;
                p[1] = acc[mt][nt][1] + bv1;
            }
            {
                int r1 = r0 + 8;
                int l = r1 >> 5, n = r1 & 31;
                float* p = out + ((size_t)(n * LSEQ + l)) * VOCAB + c;
                p[0] = acc[mt][nt][2] + bv0;
                p[1] = acc[mt][nt][3] + bv1;
            }
        }
    }
}

__global__ void k_logsoftmax(float* __restrict__ out) {
    __shared__ float red[256];
    int row = blockIdx.x;
    float* p = out + (size_t)row * VOCAB;
    int t = threadIdx.x;
    float mx = -1e30f;
    for (int i = t; i < VOCAB; i += 256) mx = fmaxf(mx, p[i]);
    red[t] = mx; __syncthreads();
    for (int o = 128; o > 0; o >>= 1) { if (t < o) red[t] = fmaxf(red[t], red[t + o]); __syncthreads(); }
    mx = red[0]; __syncthreads();
    float s = 0.f;
    for (int i = t; i < VOCAB; i += 256) s += expf(p[i] - mx);
    red[t] = s; __syncthreads();
    for (int o = 128; o > 0; o >>= 1) { if (t < o) red[t] += red[t + o]; __syncthreads(); }
    float lse = mx + logf(red[0]);
    for (int i = t; i < VOCAB; i += 256) p[i] -= lse;
}

// ---------------- launch ----------------
extern "C" void kernel_launch(void* const* d_in, const int* in_sizes, int n_in,
                              void* d_out, int out_size) {
    (void)in_sizes; (void)n_in; (void)out_size;
    const float* enc   = (const float*)d_in[0];
    const int*   tgt   = (const int*)  d_in[1];
    const float* emb   = (const float*)d_in[2];
    const float* Wa_w  = (const float*)d_in[3];
    const float* Wa_b  = (const float*)d_in[4];
    const float* Ua_w  = (const float*)d_in[5];
    const float* Ua_b  = (const float*)d_in[6];
    const float* Va_w  = (const float*)d_in[7];
    const float* Va_b  = (const float*)d_in[8];
    const float* W_ih0 = (const float*)d_in[9];
    const float* W_hh0 = (const float*)d_in[10];
    const float* b_ih0 = (const float*)d_in[11];
    const float* b_hh0 = (const float*)d_in[12];
    const float* W_ih1 = (const float*)d_in[13];
    const float* W_hh1 = (const float*)d_in[14];
    const float* b_ih1 = (const float*)d_in[15];
    const float* b_hh1 = (const float*)d_in[16];
    const float* fc_w  = (const float*)d_in[17];
    const float* fc_b  = (const float*)d_in[18];

    float* out = (float*)d_out;
    float* att = out + (size_t)NB * LSEQ * VOCAB;

    k_zero<<<256, 256>>>();
    k_cvt_fcw<<<4096, 256>>>(fc_w);
    k_uk<<<dim3(16, 64), 256>>>(enc, Ua_w, Ua_b);
    k_mega<<<GRID, 256>>>(enc, tgt, emb, Wa_w, Wa_b, Va_w, Va_b,
                          W_ih0, W_hh0, b_ih0, b_hh0,
                          W_ih1, W_hh1, b_ih1, b_hh1, att);
    k_fc<<<dim3(VOCAB / 64, NROW / 64), 256>>>(fc_b, out);
    k_logsoftmax<<<NROW, 256>>>(out);
}

// round 4
// speedup vs baseline: 2.1371x; 2.1371x over previous
#include <cuda_runtime.h>
#include <cuda_bf16.h>
#include <math.h>

typedef unsigned int uint;

#define VOCAB 32000
#define HDIM  1024
#define EHDIM 1024
#define NB    32
#define LSEQ  128
#define XDIM  2048
#define G3H   3072
#define NROW  (NB*LSEQ)
#define GRID  148
#define NBH   (NB*HDIM)
#define NBG   (NB*G3H)

// ---------------- scratch ----------------
__device__ __align__(256) float g_Uk[NB*LSEQ*HDIM];
__device__ __align__(256) float g_h0[NBH];
__device__ __align__(256) float g_h1[NBH];
__device__ __align__(256) float g_q[NB*XDIM];
__device__ __align__(256) float g_Wq4[4*NBH];
__device__ __align__(256) float g_scores[NB*LSEQ];
__device__ __align__(256) float g_x[NB*XDIM];
__device__ __align__(256) float g_gh0[2*NBG];
__device__ __align__(256) float g_gh1[2*NBG];
__device__ __align__(256) float g_gi0[4*NBG];
__device__ __align__(256) float g_gi1[2*NBG];
__device__ __align__(256) float g_wWa[HDIM*XDIM];
__device__ __align__(256) float g_wHh0[G3H*HDIM];
__device__ __align__(256) float g_wHh1[G3H*HDIM];
__device__ __align__(256) float g_wIh0[G3H*XDIM];
__device__ __align__(256) float g_wIh1[G3H*HDIM];
__device__ __align__(256) __nv_bfloat162 g_fcw2[VOCAB*HDIM/2];
__device__ __align__(256) __nv_bfloat162 g_A2[NROW*HDIM/2];
__device__ unsigned g_bar;
__device__ unsigned g_gen;

// ---------------- helpers ----------------
__device__ __forceinline__ float tf32r(float x) {
    uint r; asm("cvt.rna.tf32.f32 %0,%1;" : "=r"(r) : "f"(x)); return __uint_as_float(r);
}
__device__ __forceinline__ float tanha(float x) {
    float r; asm("tanh.approx.f32 %0,%1;" : "=f"(r) : "f"(x)); return r;
}
__device__ __forceinline__ float sigp(float x) { return 1.f / (1.f + __expf(-x)); }
__device__ __forceinline__ float wsum(float v) {
#pragma unroll
    for (int o = 16; o > 0; o >>= 1) v += __shfl_xor_sync(0xffffffffu, v, o);
    return v;
}
__device__ __forceinline__ float wmaxr(float v) {
#pragma unroll
    for (int o = 16; o > 0; o >>= 1) v = fmaxf(v, __shfl_xor_sync(0xffffffffu, v, o));
    return v;
}
__device__ __forceinline__ void cpa16(uint dst, const void* src) {
    asm volatile("cp.async.cg.shared.global [%0], [%1], 16;\n" :: "r"(dst), "l"(src));
}
#define CP_COMMIT asm volatile("cp.async.commit_group;\n")
#define CP_WAIT2  asm volatile("cp.async.wait_group 2;\n" ::: "memory")
#define CP_WAIT1  asm volatile("cp.async.wait_group 1;\n" ::: "memory")
#define CP_WAIT0  asm volatile("cp.async.wait_group 0;\n" ::: "memory")

__device__ __forceinline__ void mma_tf32(float* c, float a0, float a1, float a2, float a3,
                                         float b0, float b1) {
    asm volatile(
        "mma.sync.aligned.m16n8k8.row.col.f32.tf32.tf32.f32 "
        "{%0,%1,%2,%3},{%4,%5,%6,%7},{%8,%9},{%0,%1,%2,%3};\n"
        : "+f"(c[0]), "+f"(c[1]), "+f"(c[2]), "+f"(c[3])
        : "r"(__float_as_uint(a0)), "r"(__float_as_uint(a1)),
          "r"(__float_as_uint(a2)), "r"(__float_as_uint(a3)),
          "r"(__float_as_uint(b0)), "r"(__float_as_uint(b1)));
}
__device__ __forceinline__ void mma_bf16(float* c, uint a0, uint a1, uint a2, uint a3,
                                         uint b0, uint b1) {
    asm volatile(
        "mma.sync.aligned.m16n8k16.row.col.f32.bf16.bf16.f32 "
        "{%0,%1,%2,%3}, {%4,%5,%6,%7}, {%8,%9}, {%0,%1,%2,%3};\n"
        : "+f"(c[0]), "+f"(c[1]), "+f"(c[2]), "+f"(c[3])
        : "r"(a0), "r"(a1), "r"(a2), "r"(a3), "r"(b0), "r"(b1));
}

// ---------------- grid barrier ----------------
__device__ __forceinline__ void gsync(int nb) {
    __syncthreads();
    if (threadIdx.x == 0) {
        volatile unsigned* vg = &g_gen;
        unsigned gen = *vg;
        __threadfence();
        unsigned old = atomicInc(&g_bar, (unsigned)(nb - 1));
        if (old == (unsigned)(nb - 1)) {
            __threadfence();
            *vg = gen + 1;
        } else {
            while (*vg == gen) __nanosleep(32);
            __threadfence();
        }
    }
    __syncthreads();
}

// ---------------- tf32 mma tile: C[32][64@jbase] = A[32][512@koff] @ W^T (+bias) ----------------
#define TBUF 3456   // 32*36 + 64*36 floats per stage

__device__ void gemm_mma(const float* __restrict__ A, int lda,
                         const float* __restrict__ W, int ldw,
                         const float* __restrict__ bias, int addb,
                         float* __restrict__ C, int ldc,
                         int jbase, int koff, float* sm) {
    const int tid = threadIdx.x;
    const int lane = tid & 31, wid = tid >> 5;
    const int warpM = wid & 1, warpN = wid >> 1;   // 2 x 4 warps -> 32x64
    const int g = lane >> 2, tg = lane & 3;
    const int am = tid >> 3, ak = (tid & 7) << 2;

    float acc[2][4];
#pragma unroll
    for (int h = 0; h < 2; h++)
#pragma unroll
        for (int u = 0; u < 4; u++) acc[h][u] = 0.f;

    uint sb = (uint)__cvta_generic_to_shared(sm);

#define ISSUE(c) do { \
    int _buf = (c) % 3; uint _b = sb + (uint)(_buf * TBUF) * 4; \
    int _ko = koff + (c) * 32; \
    cpa16(_b + (uint)(am * 36 + ak) * 4, A + (size_t)am * lda + _ko + ak); \
    _Pragma("unroll") \
    for (int _i = 0; _i < 2; _i++) { \
        int _idx = tid + _i * 256; \
        int _wn = _idx >> 3, _wk = (_idx & 7) << 2; \
        cpa16(_b + (uint)(32 * 36 + _wn * 36 + _wk) * 4, \
              W + (size_t)(jbase + _wn) * ldw + _ko + _wk); \
    } } while (0)

    ISSUE(0); CP_COMMIT;
    ISSUE(1); CP_COMMIT;

    for (int c = 0; c < 16; ++c) {
        if (c + 2 < 16) { ISSUE(c + 2); CP_COMMIT; CP_WAIT2; }
        else if (c + 1 < 16) { CP_WAIT1; }
        else { CP_WAIT0; }
        __syncthreads();
        const float* bA = sm + (c % 3) * TBUF;
        const float* bW = bA + 32 * 36;
        int ar = (warpM * 16 + g) * 36;
        int br = (warpN * 16 + g) * 36;
#pragma unroll
        for (int kk = 0; kk < 4; kk++) {
            int ko = kk * 8 + tg;
            float a0 = bA[ar + ko],       a1 = bA[ar + 288 + ko];
            float a2 = bA[ar + ko + 4],   a3 = bA[ar + 288 + ko + 4];
            float b0 = bW[br + ko],       b1 = bW[br + ko + 4];
            float b2 = bW[br + 288 + ko], b3 = bW[br + 288 + ko + 4];
            mma_tf32(acc[0], a0, a1, a2, a3, b0, b1);
            mma_tf32(acc[1], a0, a1, a2, a3, b2, b3);
        }
        __syncthreads();
    }
#undef ISSUE

    int m = warpM * 16 + g;
#pragma unroll
    for (int h = 0; h < 2; h++) {
        int j = jbase + warpN * 16 + h * 8 + tg * 2;
        float bb0 = addb ? bias[j] : 0.f;
        float bb1 = addb ? bias[j + 1] : 0.f;
        C[(size_t)m * ldc + j]           = acc[h][0] + bb0;
        C[(size_t)m * ldc + j + 1]       = acc[h][1] + bb1;
        C[(size_t)(m + 8) * ldc + j]     = acc[h][2] + bb0;
        C[(size_t)(m + 8) * ldc + j + 1] = acc[h][3] + bb1;
    }
}

// ---------------- persistent megakernel ----------------
__global__ void __launch_bounds__(256, 1) k_mega(
    const float* __restrict__ enc, const int* __restrict__ tgt,
    const float* __restrict__ emb,
    const float* __restrict__ Wa_b,
    const float* __restrict__ Va_w, const float* __restrict__ Va_b,
    const float* __restrict__ bih0, const float* __restrict__ bhh0,
    const float* __restrict__ bih1, const float* __restrict__ bhh1,
    float* __restrict__ att) {
    __shared__ float sm[3 * TBUF];

    const int nbk = gridDim.x;
    const int tid = threadIdx.x;
    const int wid = tid >> 5, lane = tid & 31;
    const int gw = blockIdx.x * 8 + wid;
    const int NW = nbk * 8;
    const int gt = blockIdx.x * 256 + tid;
    const int NT = nbk * 256;
    const float Vab = Va_b[0];

    for (int step = 0; step < LSEQ; step++) {
        // ---- P1: Wq (split4, 64 tasks) + gh0 (split2, 96) + gh1 (split2, 96)
        for (int t = blockIdx.x; t < 256; t += nbk) {
            if (t < 64) {
                int p = t >> 4, jt = t & 15;
                gemm_mma(g_q, XDIM, g_wWa, XDIM, Wa_b, p == 0,
                         g_Wq4 + p * NBH, HDIM, jt * 64, p * 512, sm);
            } else if (t < 160) {
                int u = t - 64, p = u / 48, jt = u % 48;
                gemm_mma(g_h0, HDIM, g_wHh0, HDIM, bhh0, p == 0,
                         g_gh0 + p * NBG, G3H, jt * 64, p * 512, sm);
            } else {
                int u = t - 160, p = u / 48, jt = u % 48;
                gemm_mma(g_h1, HDIM, g_wHh1, HDIM, bhh1, p == 0,
                         g_gh1 + p * NBG, G3H, jt * 64, p * 512, sm);
            }
        }
        gsync(nbk);

        // ---- P2a: scores
        for (int t = gw; t < NB * LSEQ; t += NW) {
            int n = t >> 7;
            const float4* uk = (const float4*)(g_Uk + (size_t)t * HDIM);
            const float4* w0 = (const float4*)(g_Wq4 + n * HDIM);
            const float4* w1 = (const float4*)(g_Wq4 + NBH + n * HDIM);
            const float4* w2 = (const float4*)(g_Wq4 + 2 * NBH + n * HDIM);
            const float4* w3 = (const float4*)(g_Wq4 + 3 * NBH + n * HDIM);
            const float4* va = (const float4*)Va_w;
            float s = 0.f;
#pragma unroll 2
            for (int i = lane; i < 256; i += 32) {
                float4 u = uk[i], a = w0[i], b = w1[i], c2 = w2[i], d = w3[i], v = va[i];
                s += v.x * tanha(u.x + a.x + b.x + c2.x + d.x);
                s += v.y * tanha(u.y + a.y + b.y + c2.y + d.y);
                s += v.z * tanha(u.z + a.z + b.z + c2.z + d.z);
                s += v.w * tanha(u.w + a.w + b.w + c2.w + d.w);
            }
            s = wsum(s);
            if (lane == 0) g_scores[t] = s + Vab;
        }
        gsync(nbk);

        // ---- P2c: softmax + context + embedding -> g_x, att out
        for (int t = gw; t < 2048; t += NW) {
            if (t < 1024) {
                int n = t >> 5, c = t & 31, d = c * 32 + lane;
                const float* sc = g_scores + n * LSEQ;
                float e[4];
                float m0 = fmaxf(fmaxf(sc[lane * 4 + 0], sc[lane * 4 + 1]),
                                 fmaxf(sc[lane * 4 + 2], sc[lane * 4 + 3]));
                float mx = wmaxr(m0);
                float lsum = 0.f;
#pragma unroll
                for (int i = 0; i < 4; i++) { e[i] = __expf(sc[lane * 4 + i] - mx); lsum += e[i]; }
                float inv = __fdividef(1.f, wsum(lsum));
                if (c == 0) {
                    float* ap = att + ((size_t)n * LSEQ + step) * LSEQ + lane * 4;
#pragma unroll
                    for (int i = 0; i < 4; i++) ap[i] = e[i] * inv;
                }
                float ctx = 0.f;
                const float* ep = enc + (size_t)n * EHDIM + d;
#pragma unroll 4
                for (int l = 0; l < LSEQ; l++) {
                    float wl = __shfl_sync(0xffffffffu, e[l & 3], l >> 2);
                    ctx += wl * ep[(size_t)l * (NB * EHDIM)];
                }
                g_x[n * XDIM + d] = ctx * inv;
            } else {
                int u = t - 1024;
                int n = u >> 5, c = u & 31, j = c * 32 + lane;
                int tok = tgt[n * LSEQ + step];
                g_x[n * XDIM + EHDIM + j] = emb[(size_t)tok * HDIM + j];
            }
        }
        gsync(nbk);

        // ---- P3: gi0 = x@Wih0^T (split4, 192 tasks)
        for (int t = blockIdx.x; t < 192; t += nbk) {
            int p = t / 48, jt = t % 48;
            gemm_mma(g_x, XDIM, g_wIh0, XDIM, bih0, p == 0,
                     g_gi0 + p * NBG, G3H, jt * 64, p * 512, sm);
        }
        gsync(nbk);

        // ---- comb0 -> h0, q[:,0:1024]
        for (int i = gt; i < NBH; i += NT) {
            int n = i >> 10, j = i & 1023;
            int b = n * G3H + j;
            float gir = g_gi0[b] + g_gi0[NBG + b] + g_gi0[2 * NBG + b] + g_gi0[3 * NBG + b];
            float giz = g_gi0[b + HDIM] + g_gi0[NBG + b + HDIM] + g_gi0[2 * NBG + b + HDIM] + g_gi0[3 * NBG + b + HDIM];
            float gin = g_gi0[b + 2 * HDIM] + g_gi0[NBG + b + 2 * HDIM] + g_gi0[2 * NBG + b + 2 * HDIM] + g_gi0[3 * NBG + b + 2 * HDIM];
            float ghr = g_gh0[b] + g_gh0[NBG + b];
            float ghz = g_gh0[b + HDIM] + g_gh0[NBG + b + HDIM];
            float ghn = g_gh0[b + 2 * HDIM] + g_gh0[NBG + b + 2 * HDIM];
            float r = sigp(gir + ghr);
            float z = sigp(giz + ghz);
            float nn = tanhf(gin + r * ghn);
            float h = (1.f - z) * nn + z * g_h0[i];
            g_h0[i] = h;
            g_q[n * XDIM + j] = h;
        }
        gsync(nbk);

        // ---- P4: gi1 = h0@Wih1^T (split2, 96 tasks)
        for (int t = blockIdx.x; t < 96; t += nbk) {
            int p = t / 48, jt = t % 48;
            gemm_mma(g_h0, HDIM, g_wIh1, HDIM, bih1, p == 0,
                     g_gi1 + p * NBG, G3H, jt * 64, p * 512, sm);
        }
        gsync(nbk);

        // ---- comb1 -> h1, q[:,1024:2048], A2
        for (int i = gt; i < NBH; i += NT) {
            int n = i >> 10, j = i & 1023;
            int b = n * G3H + j;
            float gir = g_gi1[b] + g_gi1[NBG + b];
            float giz = g_gi1[b + HDIM] + g_gi1[NBG + b + HDIM];
            float gin = g_gi1[b + 2 * HDIM] + g_gi1[NBG + b + 2 * HDIM];
            float ghr = g_gh1[b] + g_gh1[NBG + b];
            float ghz = g_gh1[b + HDIM] + g_gh1[NBG + b + HDIM];
            float ghn = g_gh1[b + 2 * HDIM] + g_gh1[NBG + b + 2 * HDIM];
            float r = sigp(gir + ghr);
            float z = sigp(giz + ghz);
            float nn = tanhf(gin + r * ghn);
            float h = (1.f - z) * nn + z * g_h1[i];
            g_h1[i] = h;
            g_q[n * XDIM + HDIM + j] = h;
            ((__nv_bfloat16*)g_A2)[(size_t)(step * NB + n) * HDIM + j] = __float2bfloat16(h);
        }
        gsync(nbk);
    }
}

// ---------------- init / conversions ----------------
__global__ void k_zero() {
    int i = blockIdx.x * 256 + threadIdx.x;
    if (i == 0) { g_bar = 0; g_gen = 0; }
    if (i < NBH) { g_h0[i] = 0.f; g_h1[i] = 0.f; }
    if (i < NB * XDIM) { g_q[i] = 0.f; }
}

__global__ void k_cvtw(const float* __restrict__ wa, const float* __restrict__ hh0,
                       const float* __restrict__ hh1, const float* __restrict__ ih0,
                       const float* __restrict__ ih1) {
    int st = gridDim.x * blockDim.x;
    int i0 = blockIdx.x * blockDim.x + threadIdx.x;
    for (int i = i0; i < HDIM * XDIM; i += st) g_wWa[i] = tf32r(wa[i]);
    for (int i = i0; i < G3H * HDIM; i += st) {
        g_wHh0[i] = tf32r(hh0[i]);
        g_wHh1[i] = tf32r(hh1[i]);
        g_wIh1[i] = tf32r(ih1[i]);
    }
    for (int i = i0; i < G3H * XDIM; i += st) g_wIh0[i] = tf32r(ih0[i]);
}

__global__ void k_cvt_fcw(const float* __restrict__ w) {
    int stride = gridDim.x * blockDim.x;
    for (int i = blockIdx.x * blockDim.x + threadIdx.x; i < VOCAB * HDIM / 2; i += stride) {
        float2 f = ((const float2*)w)[i];
        g_fcw2[i] = __floats2bfloat162_rn(f.x, f.y);
    }
}

// ---------------- Uk = keys @ Ua_w^T + Ua_b ----------------
__global__ void k_uk(const float* __restrict__ enc, const float* __restrict__ Uw,
                     const float* __restrict__ Ub) {
    __shared__ float As[16][68];
    __shared__ float Bs[16][68];
    int bm = blockIdx.y, bn = blockIdx.x;
    int tid = threadIdx.x;
    int tm = (tid >> 4) << 2;
    int tn = (tid & 15) << 2;
    float acc[4][4];
#pragma unroll
    for (int i = 0; i < 4; i++)
#pragma unroll
        for (int j = 0; j < 4; j++) acc[i][j] = 0.f;

    int lm = tid >> 2;
    int lk = (tid & 3) << 2;
    int r = bm * 64 + lm;
    int nb = r >> 7;
    int lb = r & 127;
    const float* Arow = enc + ((size_t)lb * NB + nb) * EHDIM;
    const float* Brow = Uw + (size_t)(bn * 64 + lm) * EHDIM;

    for (int k0 = 0; k0 < EHDIM; k0 += 16) {
        float4 av = *(const float4*)(Arow + k0 + lk);
        float4 bv = *(const float4*)(Brow + k0 + lk);
        As[lk + 0][lm] = av.x; As[lk + 1][lm] = av.y; As[lk + 2][lm] = av.z; As[lk + 3][lm] = av.w;
        Bs[lk + 0][lm] = bv.x; Bs[lk + 1][lm] = bv.y; Bs[lk + 2][lm] = bv.z; Bs[lk + 3][lm] = bv.w;
        __syncthreads();
#pragma unroll
        for (int kk = 0; kk < 16; kk++) {
            float a[4], b[4];
#pragma unroll
            for (int i = 0; i < 4; i++) { a[i] = As[kk][tm + i]; b[i] = Bs[kk][tn + i]; }
#pragma unroll
            for (int i = 0; i < 4; i++)
#pragma unroll
                for (int j = 0; j < 4; j++) acc[i][j] += a[i] * b[j];
        }
        __syncthreads();
    }
#pragma unroll
    for (int i = 0; i < 4; i++) {
        int rr = bm * 64 + tm + i;
#pragma unroll
        for (int j = 0; j < 4; j++) {
            int c = bn * 64 + tn + j;
            g_Uk[(size_t)rr * HDIM + c] = acc[i][j] + Ub[c];
        }
    }
}

// ---------------- FC (bf16 mma) + log_softmax ----------------
__global__ void __launch_bounds__(256) k_fc(const float* __restrict__ fcb, float* __restrict__ out) {
    __shared__ __nv_bfloat16 As[64][18];
    __shared__ __nv_bfloat16 Bs[64][18];
    int bm = blockIdx.y, bn = blockIdx.x;
    int tid = threadIdx.x, wid = tid >> 5, lane = tid & 31;
    int g = lane >> 2, tg = lane & 3;
    int warpM = wid >> 2, warpN = wid & 3;
    float acc[2][2][4];
#pragma unroll
    for (int a = 0; a < 2; a++)
#pragma unroll
        for (int b = 0; b < 2; b++)
#pragma unroll
            for (int c = 0; c < 4; c++) acc[a][b][c] = 0.f;

    const uint* Ag = (const uint*)g_A2;
    const uint* Bg = (const uint*)g_fcw2;

    for (int kt = 0; kt < 64; kt++) {
#pragma unroll
        for (int i = 0; i < 2; i++) {
            int idx = tid + i * 256;
            int m = idx >> 3, p = idx & 7;
            *(uint*)&As[m][p * 2] = Ag[(size_t)(bm * 64 + m) * 512 + kt * 8 + p];
            *(uint*)&Bs[m][p * 2] = Bg[(size_t)(bn * 64 + m) * 512 + kt * 8 + p];
        }
        __syncthreads();
#pragma unroll
        for (int mt = 0; mt < 2; mt++) {
            int m0 = warpM * 32 + mt * 16;
            uint a0 = *(const uint*)&As[m0 + g][tg * 2];
            uint a1 = *(const uint*)&As[m0 + g + 8][tg * 2];
            uint a2 = *(const uint*)&As[m0 + g][8 + tg * 2];
            uint a3 = *(const uint*)&As[m0 + g + 8][8 + tg * 2];
#pragma unroll
            for (int nt = 0; nt < 2; nt++) {
                int n0 = warpN * 16 + nt * 8;
                uint b0 = *(const uint*)&Bs[n0 + g][tg * 2];
                uint b1 = *(const uint*)&Bs[n0 + g][8 + tg * 2];
                mma_bf16(acc[mt][nt], a0, a1, a2, a3, b0, b1);
            }
        }
        __syncthreads();
    }
#pragma unroll
    for (int mt = 0; mt < 2; mt++) {
#pragma unroll
        for (int nt = 0; nt < 2; nt++) {
            int r0 = bm * 64 + warpM * 32 + mt * 16 + g;
            int c = bn * 64 + warpN * 16 + nt * 8 + tg * 2;
            float bv0 = fcb[c], bv1 = fcb[c + 1];
            {
                int l = r0 >> 5, n = r0 & 31;
                float* p = out + ((size_t)(n * LSEQ + l)) * VOCAB + c;
                p[0] = acc[mt][nt][0] + bv0;
                p[1] = acc[mt][nt][1] + bv1;
            }
            {
                int r1 = r0 + 8;
                int l = r1 >> 5, n = r1 & 31;
                float* p = out + ((size_t)(n * LSEQ + l)) * VOCAB + c;
                p[0] = acc[mt][nt][2] + bv0;
                p[1] = acc[mt][nt][3] + bv1;
            }
        }
    }
}

__global__ void k_logsoftmax(float* __restrict__ out) {
    __shared__ float red[256];
    int row = blockIdx.x;
    float* p = out + (size_t)row * VOCAB;
    int t = threadIdx.x;
    float mx = -1e30f;
    for (int i = t; i < VOCAB; i += 256) mx = fmaxf(mx, p[i]);
    red[t] = mx; __syncthreads();
    for (int o = 128; o > 0; o >>= 1) { if (t < o) red[t] = fmaxf(red[t], red[t + o]); __syncthreads(); }
    mx = red[0]; __syncthreads();
    float s = 0.f;
    for (int i = t; i < VOCAB; i += 256) s += __expf(p[i] - mx);
    red[t] = s; __syncthreads();
    for (int o = 128; o > 0; o >>= 1) { if (t < o) red[t] += red[t + o]; __syncthreads(); }
    float lse = mx + logf(red[0]);
    for (int i = t; i < VOCAB; i += 256) p[i] -= lse;
}

// ---------------- launch ----------------
extern "C" void kernel_launch(void* const* d_in, const int* in_sizes, int n_in,
                              void* d_out, int out_size) {
    (void)in_sizes; (void)n_in; (void)out_size;
    const float* enc   = (const float*)d_in[0];
    const int*   tgt   = (const int*)  d_in[1];
    const float* emb   = (const float*)d_in[2];
    const float* Wa_w  = (const float*)d_in[3];
    const float* Wa_b  = (const float*)d_in[4];
    const float* Ua_w  = (const float*)d_in[5];
    const float* Ua_b  = (const float*)d_in[6];
    const float* Va_w  = (const float*)d_in[7];
    const float* Va_b  = (const float*)d_in[8];
    const float* W_ih0 = (const float*)d_in[9];
    const float* W_hh0 = (const float*)d_in[10];
    const float* b_ih0 = (const float*)d_in[11];
    const float* b_hh0 = (const float*)d_in[12];
    const float* W_ih1 = (const float*)d_in[13];
    const float* W_hh1 = (const float*)d_in[14];
    const float* b_ih1 = (const float*)d_in[15];
    const float* b_hh1 = (const float*)d_in[16];
    const float* fc_w  = (const float*)d_in[17];
    const float* fc_b  = (const float*)d_in[18];

    float* out = (float*)d_out;
    float* att = out + (size_t)NB * LSEQ * VOCAB;

    k_zero<<<256, 256>>>();
    k_cvtw<<<1024, 256>>>(Wa_w, W_hh0, W_hh1, W_ih0, W_ih1);
    k_cvt_fcw<<<4096, 256>>>(fc_w);
    k_uk<<<dim3(16, 64), 256>>>(enc, Ua_w, Ua_b);
    k_mega<<<GRID, 256>>>(enc, tgt, emb, Wa_b, Va_w, Va_b,
                          b_ih0, b_hh0, b_ih1, b_hh1, att);
    k_fc<<<dim3(VOCAB / 64, NROW / 64), 256>>>(fc_b, out);
    k_logsoftmax<<<NROW, 256>>>(out);
}

// round 5
// speedup vs baseline: 2.7193x; 1.2724x over previous
#include <cuda_runtime.h>
#include <cuda_bf16.h>
#include <math.h>

typedef unsigned int uint;

#define VOCAB 32000
#define HDIM  1024
#define EHDIM 1024
#define NB    32
#define LSEQ  128
#define XDIM  2048
#define G3H   3072
#define NROW  (NB*LSEQ)
#define NBH   (NB*HDIM)
#define NBG   (NB*G3H)

// ---------------- scratch ----------------
__device__ __align__(256) float g_Uk[NB*LSEQ*HDIM];
__device__ __align__(256) float g_h0[NBH];
__device__ __align__(256) float g_h1[NBH];
__device__ __align__(256) float g_q[NB*XDIM];
__device__ __align__(256) float g_Wq[NBH];
__device__ __align__(256) float g_scores[NB*LSEQ];
__device__ __align__(256) float g_x[NB*XDIM];
__device__ __align__(256) float g_gh0[NBG];
__device__ __align__(256) float g_gh1[NBG];
__device__ __align__(256) float g_gi0[NBG];
__device__ __align__(256) float g_gi1[NBG];
__device__ __align__(256) float g_wWa[HDIM*XDIM];
__device__ __align__(256) float g_wHh0[G3H*HDIM];
__device__ __align__(256) float g_wHh1[G3H*HDIM];
__device__ __align__(256) float g_wIh0[G3H*XDIM];
__device__ __align__(256) float g_wIh1[G3H*HDIM];
__device__ __align__(256) __nv_bfloat162 g_fcw2[VOCAB*HDIM/2];
__device__ __align__(256) __nv_bfloat162 g_A2[NROW*HDIM/2];
__device__ unsigned g_bar;
__device__ unsigned g_gen;

// ---------------- helpers ----------------
__device__ __forceinline__ float tf32r(float x) {
    uint r; asm("cvt.rna.tf32.f32 %0,%1;" : "=r"(r) : "f"(x)); return __uint_as_float(r);
}
__device__ __forceinline__ float tanha(float x) {
    float r; asm("tanh.approx.f32 %0,%1;" : "=f"(r) : "f"(x)); return r;
}
__device__ __forceinline__ float sigp(float x) { return 1.f / (1.f + __expf(-x)); }
__device__ __forceinline__ float wsum(float v) {
#pragma unroll
    for (int o = 16; o > 0; o >>= 1) v += __shfl_xor_sync(0xffffffffu, v, o);
    return v;
}
__device__ __forceinline__ float wmaxr(float v) {
#pragma unroll
    for (int o = 16; o > 0; o >>= 1) v = fmaxf(v, __shfl_xor_sync(0xffffffffu, v, o));
    return v;
}
__device__ __forceinline__ void cpa16(uint dst, const void* src) {
    asm volatile("cp.async.cg.shared.global [%0], [%1], 16;\n" :: "r"(dst), "l"(src));
}
#define CP_COMMIT asm volatile("cp.async.commit_group;\n")
#define CP_WAIT1  asm volatile("cp.async.wait_group 1;\n" ::: "memory")
#define CP_WAIT0  asm volatile("cp.async.wait_group 0;\n" ::: "memory")

__device__ __forceinline__ void mma_tf32(float* c, float a0, float a1, float a2, float a3,
                                         float b0, float b1) {
    asm volatile(
        "mma.sync.aligned.m16n8k8.row.col.f32.tf32.tf32.f32 "
        "{%0,%1,%2,%3},{%4,%5,%6,%7},{%8,%9},{%0,%1,%2,%3};\n"
        : "+f"(c[0]), "+f"(c[1]), "+f"(c[2]), "+f"(c[3])
        : "r"(__float_as_uint(a0)), "r"(__float_as_uint(a1)),
          "r"(__float_as_uint(a2)), "r"(__float_as_uint(a3)),
          "r"(__float_as_uint(b0)), "r"(__float_as_uint(b1)));
}
__device__ __forceinline__ void mma_bf16(float* c, uint a0, uint a1, uint a2, uint a3,
                                         uint b0, uint b1) {
    asm volatile(
        "mma.sync.aligned.m16n8k16.row.col.f32.bf16.bf16.f32 "
        "{%0,%1,%2,%3}, {%4,%5,%6,%7}, {%8,%9}, {%0,%1,%2,%3};\n"
        : "+f"(c[0]), "+f"(c[1]), "+f"(c[2]), "+f"(c[3])
        : "r"(a0), "r"(a1), "r"(a2), "r"(a3), "r"(b0), "r"(b1));
}

// ---------------- grid barrier (no nanosleep; IVALL via threadfence on exit) ----------------
__device__ __forceinline__ void gsync(int nb) {
    __syncthreads();
    if (threadIdx.x == 0) {
        volatile unsigned* vg = &g_gen;
        unsigned gen = *vg;
        __threadfence();
        unsigned old = atomicInc(&g_bar, (unsigned)(nb - 1));
        if (old == (unsigned)(nb - 1)) {
            __threadfence();
            *vg = gen + 1;
        } else {
            while (*vg == gen) { }
            __threadfence();
        }
    }
    __syncthreads();
}

// ---------------- tf32 mma tile: C[32][64@jbase] += A[32][512@koff] @ W^T (atomic) -------
#define TBUF 3456   // (32 + 64) * 36 floats per stage

__device__ void gemm_mma(const float* __restrict__ A, int lda,
                         const float* __restrict__ W, int ldw,
                         float* __restrict__ C, int ldc,
                         int jbase, int koff, float* sm) {
    const int tid = threadIdx.x;
    const int lane = tid & 31, wid = tid >> 5;
    const int warpM = wid & 1, warpN = wid >> 1;   // 2 x 4 warps -> 32x64
    const int g = lane >> 2, tg = lane & 3;
    const int am = tid >> 3, ak = (tid & 7) << 2;

    float acc[2][4];
#pragma unroll
    for (int h = 0; h < 2; h++)
#pragma unroll
        for (int u = 0; u < 4; u++) acc[h][u] = 0.f;

    uint sb = (uint)__cvta_generic_to_shared(sm);

#define ISSUE(c) do { \
    uint _b = sb + (uint)(((c) & 1) * TBUF) * 4; \
    int _ko = koff + (c) * 32; \
    cpa16(_b + (uint)(am * 36 + ak) * 4, A + (size_t)am * lda + _ko + ak); \
    _Pragma("unroll") \
    for (int _i = 0; _i < 2; _i++) { \
        int _idx = tid + _i * 256; \
        int _wn = _idx >> 3, _wk = (_idx & 7) << 2; \
        cpa16(_b + (uint)(32 * 36 + _wn * 36 + _wk) * 4, \
              W + (size_t)(jbase + _wn) * ldw + _ko + _wk); \
    } } while (0)

    ISSUE(0); CP_COMMIT;

    for (int c = 0; c < 16; ++c) {
        if (c + 1 < 16) { ISSUE(c + 1); CP_COMMIT; CP_WAIT1; }
        else { CP_WAIT0; }
        __syncthreads();
        const float* bA = sm + (c & 1) * TBUF;
        const float* bW = bA + 32 * 36;
        int ar = (warpM * 16 + g) * 36;
        int br = (warpN * 16 + g) * 36;
#pragma unroll
        for (int kk = 0; kk < 4; kk++) {
            int ko = kk * 8 + tg;
            float a0 = bA[ar + ko],       a1 = bA[ar + 288 + ko];
            float a2 = bA[ar + ko + 4],   a3 = bA[ar + 288 + ko + 4];
            float b0 = bW[br + ko],       b1 = bW[br + ko + 4];
            float b2 = bW[br + 288 + ko], b3 = bW[br + 288 + ko + 4];
            mma_tf32(acc[0], a0, a1, a2, a3, b0, b1);
            mma_tf32(acc[1], a0, a1, a2, a3, b2, b3);
        }
        __syncthreads();
    }
#undef ISSUE

    int m = warpM * 16 + g;
#pragma unroll
    for (int h = 0; h < 2; h++) {
        int j = jbase + warpN * 16 + h * 8 + tg * 2;
        atomicAdd(&C[(size_t)m * ldc + j],           acc[h][0]);
        atomicAdd(&C[(size_t)m * ldc + j + 1],       acc[h][1]);
        atomicAdd(&C[(size_t)(m + 8) * ldc + j],     acc[h][2]);
        atomicAdd(&C[(size_t)(m + 8) * ldc + j + 1], acc[h][3]);
    }
}

// bias presets (256 threads)
__device__ __forceinline__ void preset3h(float* dst, const float* bias, int n) {
    float* p = dst + (size_t)n * G3H;
#pragma unroll
    for (int j = threadIdx.x; j < G3H; j += 256) p[j] = bias[j];
}
__device__ __forceinline__ void preset1h(float* dst, const float* bias, int n) {
    float* p = dst + (size_t)n * HDIM;
    for (int j = threadIdx.x; j < HDIM; j += 256) p[j] = bias[j];
}

// ---------------- persistent megakernel ----------------
__global__ void __launch_bounds__(256, 2) k_mega(
    const float* __restrict__ enc, const int* __restrict__ tgt,
    const float* __restrict__ emb,
    const float* __restrict__ Wa_b,
    const float* __restrict__ Va_w, const float* __restrict__ Va_b,
    const float* __restrict__ bih0, const float* __restrict__ bhh0,
    const float* __restrict__ bih1, const float* __restrict__ bhh1,
    float* __restrict__ att) {
    __shared__ float sm[2 * TBUF];

    const int nbk = gridDim.x;
    const int tid = threadIdx.x;
    const int wid = tid >> 5, lane = tid & 31;
    const int gw = blockIdx.x * 8 + wid;
    const int NW = nbk * 8;
    const int gt = blockIdx.x * 256 + tid;
    const int NT = nbk * 256;
    const float Vab = Va_b[0];

    for (int step = 0; step < LSEQ; step++) {
        // ---- P1: Wq x4 (64) + gh0 x2 (96) + gh1 x2 (96) + preset gi1 (32) = 288 tasks
        for (int t = blockIdx.x; t < 288; t += nbk) {
            if (t < 64) {
                int p = t >> 4, jt = t & 15;
                gemm_mma(g_q, XDIM, g_wWa, XDIM, g_Wq, HDIM, jt * 64, p * 512, sm);
            } else if (t < 160) {
                int u = t - 64, p = u / 48, jt = u % 48;
                gemm_mma(g_h0, HDIM, g_wHh0, HDIM, g_gh0, G3H, jt * 64, p * 512, sm);
            } else if (t < 256) {
                int u = t - 160, p = u / 48, jt = u % 48;
                gemm_mma(g_h1, HDIM, g_wHh1, HDIM, g_gh1, G3H, jt * 64, p * 512, sm);
            } else {
                preset3h(g_gi1, bih1, t - 256);
            }
        }
        gsync(nbk);

        // ---- P2a: scores = Va . tanh(Wq[n] + Uk[n][l]) + Vab
        for (int t = gw; t < NB * LSEQ; t += NW) {
            int n = t >> 7;
            const float4* uk = (const float4*)(g_Uk + (size_t)t * HDIM);
            const float4* wq = (const float4*)(g_Wq + n * HDIM);
            const float4* va = (const float4*)Va_w;
            float s = 0.f;
#pragma unroll 2
            for (int i = lane; i < 256; i += 32) {
                float4 u = uk[i], q = wq[i], v = va[i];
                s += v.x * tanha(u.x + q.x);
                s += v.y * tanha(u.y + q.y);
                s += v.z * tanha(u.z + q.z);
                s += v.w * tanha(u.w + q.w);
            }
            s = wsum(s);
            if (lane == 0) g_scores[t] = s + Vab;
        }
        gsync(nbk);

        // ---- P2c: softmax + context + embedding -> g_x, att out
        for (int t = gw; t < 2048; t += NW) {
            if (t < 1024) {
                int n = t >> 5, c = t & 31, d = c * 32 + lane;
                const float* sc = g_scores + n * LSEQ;
                float e[4];
                float m0 = fmaxf(fmaxf(sc[lane * 4 + 0], sc[lane * 4 + 1]),
                                 fmaxf(sc[lane * 4 + 2], sc[lane * 4 + 3]));
                float mx = wmaxr(m0);
                float lsum = 0.f;
#pragma unroll
                for (int i = 0; i < 4; i++) { e[i] = __expf(sc[lane * 4 + i] - mx); lsum += e[i]; }
                float inv = __fdividef(1.f, wsum(lsum));
                if (c == 0) {
                    float* ap = att + ((size_t)n * LSEQ + step) * LSEQ + lane * 4;
#pragma unroll
                    for (int i = 0; i < 4; i++) ap[i] = e[i] * inv;
                }
                float ctx = 0.f;
                const float* ep = enc + (size_t)n * EHDIM + d;
#pragma unroll 4
                for (int l = 0; l < LSEQ; l++) {
                    float wl = __shfl_sync(0xffffffffu, e[l & 3], l >> 2);
                    ctx += wl * ep[(size_t)l * (NB * EHDIM)];
                }
                g_x[n * XDIM + d] = ctx * inv;
            } else {
                int u = t - 1024;
                int n = u >> 5, c = u & 31, j = c * 32 + lane;
                int tok = tgt[n * LSEQ + step];
                g_x[n * XDIM + EHDIM + j] = emb[(size_t)tok * HDIM + j];
            }
        }
        gsync(nbk);

        // ---- P3: gi0 x4 (192) + preset Wq (32) = 224 tasks
        for (int t = blockIdx.x; t < 224; t += nbk) {
            if (t < 192) {
                int p = t / 48, jt = t % 48;
                gemm_mma(g_x, XDIM, g_wIh0, XDIM, g_gi0, G3H, jt * 64, p * 512, sm);
            } else {
                preset1h(g_Wq, Wa_b, t - 192);
            }
        }
        gsync(nbk);

        // ---- comb0 -> h0, q[:,0:1024]; preset gh0 in-place
        for (int i = gt; i < NBH; i += NT) {
            int n = i >> 10, j = i & 1023;
            int b = n * G3H + j;
            float r = sigp(g_gi0[b] + g_gh0[b]);
            float z = sigp(g_gi0[b + HDIM] + g_gh0[b + HDIM]);
            float nn = tanhf(g_gi0[b + 2 * HDIM] + r * g_gh0[b + 2 * HDIM]);
            float h = (1.f - z) * nn + z * g_h0[i];
            g_h0[i] = h;
            g_q[n * XDIM + j] = h;
            g_gh0[b] = bhh0[j];
            g_gh0[b + HDIM] = bhh0[j + HDIM];
            g_gh0[b + 2 * HDIM] = bhh0[j + 2 * HDIM];
        }
        gsync(nbk);

        // ---- P4: gi1 x2 (96) + preset gi0 (32) = 128 tasks
        for (int t = blockIdx.x; t < 128; t += nbk) {
            if (t < 96) {
                int p = t / 48, jt = t % 48;
                gemm_mma(g_h0, HDIM, g_wIh1, HDIM, g_gi1, G3H, jt * 64, p * 512, sm);
            } else {
                preset3h(g_gi0, bih0, t - 96);
            }
        }
        gsync(nbk);

        // ---- comb1 -> h1, q[:,1024:2048], A2; preset gh1 in-place
        for (int i = gt; i < NBH; i += NT) {
            int n = i >> 10, j = i & 1023;
            int b = n * G3H + j;
            float r = sigp(g_gi1[b] + g_gh1[b]);
            float z = sigp(g_gi1[b + HDIM] + g_gh1[b + HDIM]);
            float nn = tanhf(g_gi1[b + 2 * HDIM] + r * g_gh1[b + 2 * HDIM]);
            float h = (1.f - z) * nn + z * g_h1[i];
            g_h1[i] = h;
            g_q[n * XDIM + HDIM + j] = h;
            ((__nv_bfloat16*)g_A2)[(size_t)(step * NB + n) * HDIM + j] = __float2bfloat16(h);
            g_gh1[b] = bhh1[j];
            g_gh1[b + HDIM] = bhh1[j + HDIM];
            g_gh1[b + 2 * HDIM] = bhh1[j + 2 * HDIM];
        }
        gsync(nbk);
    }
}

// ---------------- init: zero state, preset accumulators with biases ----------------
__global__ void k_init(const float* __restrict__ Wa_b,
                       const float* __restrict__ bhh0, const float* __restrict__ bhh1,
                       const float* __restrict__ bih0, const float* __restrict__ bih1) {
    int i0 = blockIdx.x * 256 + threadIdx.x;
    int st = gridDim.x * 256;
    if (i0 == 0) { g_bar = 0; g_gen = 0; }
    for (int i = i0; i < NBH; i += st) { g_h0[i] = 0.f; g_h1[i] = 0.f; g_Wq[i] = Wa_b[i & 1023]; }
    for (int i = i0; i < NB * XDIM; i += st) g_q[i] = 0.f;
    for (int i = i0; i < NBG; i += st) {
        int j = i % G3H;
        g_gh0[i] = bhh0[j]; g_gh1[i] = bhh1[j];
        g_gi0[i] = bih0[j]; g_gi1[i] = bih1[j];
    }
}

__global__ void k_cvtw(const float* __restrict__ wa, const float* __restrict__ hh0,
                       const float* __restrict__ hh1, const float* __restrict__ ih0,
                       const float* __restrict__ ih1) {
    int st = gridDim.x * blockDim.x;
    int i0 = blockIdx.x * blockDim.x + threadIdx.x;
    for (int i = i0; i < HDIM * XDIM; i += st) g_wWa[i] = tf32r(wa[i]);
    for (int i = i0; i < G3H * HDIM; i += st) {
        g_wHh0[i] = tf32r(hh0[i]);
        g_wHh1[i] = tf32r(hh1[i]);
        g_wIh1[i] = tf32r(ih1[i]);
    }
    for (int i = i0; i < G3H * XDIM; i += st) g_wIh0[i] = tf32r(ih0[i]);
}

__global__ void k_cvt_fcw(const float* __restrict__ w) {
    int stride = gridDim.x * blockDim.x;
    for (int i = blockIdx.x * blockDim.x + threadIdx.x; i < VOCAB * HDIM / 2; i += stride) {
        float2 f = ((const float2*)w)[i];
        g_fcw2[i] = __floats2bfloat162_rn(f.x, f.y);
    }
}

// ---------------- Uk = keys @ Ua_w^T + Ua_b (fp32, runs once) ----------------
__global__ void k_uk(const float* __restrict__ enc, const float* __restrict__ Uw,
                     const float* __restrict__ Ub) {
    __shared__ float As[16][68];
    __shared__ float Bs[16][68];
    int bm = blockIdx.y, bn = blockIdx.x;
    int tid = threadIdx.x;
    int tm = (tid >> 4) << 2;
    int tn = (tid & 15) << 2;
    float acc[4][4];
#pragma unroll
    for (int i = 0; i < 4; i++)
#pragma unroll
        for (int j = 0; j < 4; j++) acc[i][j] = 0.f;

    int lm = tid >> 2;
    int lk = (tid & 3) << 2;
    int r = bm * 64 + lm;
    int nb = r >> 7;
    int lb = r & 127;
    const float* Arow = enc + ((size_t)lb * NB + nb) * EHDIM;
    const float* Brow = Uw + (size_t)(bn * 64 + lm) * EHDIM;

    for (int k0 = 0; k0 < EHDIM; k0 += 16) {
        float4 av = *(const float4*)(Arow + k0 + lk);
        float4 bv = *(const float4*)(Brow + k0 + lk);
        As[lk + 0][lm] = av.x; As[lk + 1][lm] = av.y; As[lk + 2][lm] = av.z; As[lk + 3][lm] = av.w;
        Bs[lk + 0][lm] = bv.x; Bs[lk + 1][lm] = bv.y; Bs[lk + 2][lm] = bv.z; Bs[lk + 3][lm] = bv.w;
        __syncthreads();
#pragma unroll
        for (int kk = 0; kk < 16; kk++) {
            float a[4], b[4];
#pragma unroll
            for (int i = 0; i < 4; i++) { a[i] = As[kk][tm + i]; b[i] = Bs[kk][tn + i]; }
#pragma unroll
            for (int i = 0; i < 4; i++)
#pragma unroll
                for (int j = 0; j < 4; j++) acc[i][j] += a[i] * b[j];
        }
        __syncthreads();
    }
#pragma unroll
    for (int i = 0; i < 4; i++) {
        int rr = bm * 64 + tm + i;
#pragma unroll
        for (int j = 0; j < 4; j++) {
            int c = bn * 64 + tn + j;
            g_Uk[(size_t)rr * HDIM + c] = acc[i][j] + Ub[c];
        }
    }
}

// ---------------- FC: 128x128 bf16 mma tiles, cp.async double-buffered ----------------
__global__ void __launch_bounds__(256) k_fc(const float* __restrict__ fcb,
                                            float* __restrict__ out) {
    __shared__ __nv_bfloat16 As[2][128][24];
    __shared__ __nv_bfloat16 Bs[2][128][24];
    int bm = blockIdx.y, bn = blockIdx.x;
    int tid = threadIdx.x, wid = tid >> 5, lane = tid & 31;
    int g = lane >> 2, tg = lane & 3;
    int warpM = wid >> 2, warpN = wid & 3;   // 2 x 4 warps; warp tile 64x32

    float acc[4][4][4];
#pragma unroll
    for (int a = 0; a < 4; a++)
#pragma unroll
        for (int b = 0; b < 4; b++)
#pragma unroll
            for (int c = 0; c < 4; c++) acc[a][b][c] = 0.f;

    const __nv_bfloat16* Ag = (const __nv_bfloat16*)g_A2;
    const __nv_bfloat16* Bg = (const __nv_bfloat16*)g_fcw2;
    int srow = tid >> 1, shalf = (tid & 1) * 8;
    uint sa = (uint)__cvta_generic_to_shared(&As[0][srow][shalf]);
    uint sbb = (uint)__cvta_generic_to_shared(&Bs[0][srow][shalf]);
    const __nv_bfloat16* agp = Ag + (size_t)(bm * 128 + srow) * HDIM + shalf;
    const __nv_bfloat16* bgp = Bg + (size_t)(bn * 128 + srow) * HDIM + shalf;
    const uint BUFB = 128 * 24 * 2;  // bytes per buffer

#define FISSUE(kt) do { uint _o = ((kt) & 1) * BUFB; \
    cpa16(sa + _o, agp + (kt) * 16); cpa16(sbb + _o, bgp + (kt) * 16); } while (0)

    FISSUE(0); CP_COMMIT;

    for (int kt = 0; kt < 64; kt++) {
        if (kt + 1 < 64) { FISSUE(kt + 1); CP_COMMIT; CP_WAIT1; }
        else { CP_WAIT0; }
        __syncthreads();
        int b = kt & 1;
        uint af[4][4], bf[4][2];
#pragma unroll
        for (int mt = 0; mt < 4; mt++) {
            int m0 = warpM * 64 + mt * 16 + g;
            af[mt][0] = *(const uint*)&As[b][m0][tg * 2];
            af[mt][1] = *(const uint*)&As[b][m0 + 8][tg * 2];
            af[mt][2] = *(const uint*)&As[b][m0][8 + tg * 2];
            af[mt][3] = *(const uint*)&As[b][m0 + 8][8 + tg * 2];
        }
#pragma unroll
        for (int nt = 0; nt < 4; nt++) {
            int n0 = warpN * 32 + nt * 8 + g;
            bf[nt][0] = *(const uint*)&Bs[b][n0][tg * 2];
            bf[nt][1] = *(const uint*)&Bs[b][n0][8 + tg * 2];
        }
#pragma unroll
        for (int mt = 0; mt < 4; mt++)
#pragma unroll
            for (int nt = 0; nt < 4; nt++)
                mma_bf16(acc[mt][nt], af[mt][0], af[mt][1], af[mt][2], af[mt][3],
                         bf[nt][0], bf[nt][1]);
        __syncthreads();
    }
#undef FISSUE

#pragma unroll
    for (int mt = 0; mt < 4; mt++) {
#pragma unroll
        for (int nt = 0; nt < 4; nt++) {
            int r0 = bm * 128 + warpM * 64 + mt * 16 + g;
            int c = bn * 128 + warpN * 32 + nt * 8 + tg * 2;
            float bv0 = fcb[c], bv1 = fcb[c + 1];
            {
                int l = r0 >> 5, n = r0 & 31;
                float* p = out + ((size_t)(n * LSEQ + l)) * VOCAB + c;
                p[0] = acc[mt][nt][0] + bv0;
                p[1] = acc[mt][nt][1] + bv1;
            }
            {
                int r1 = r0 + 8;
                int l = r1 >> 5, n = r1 & 31;
                float* p = out + ((size_t)(n * LSEQ + l)) * VOCAB + c;
                p[0] = acc[mt][nt][2] + bv0;
                p[1] = acc[mt][nt][3] + bv1;
            }
        }
    }
}

// ---------------- log_softmax: online max/sum pass + subtract pass ----------------
__global__ void k_logsoftmax(float* __restrict__ out) {
    __shared__ float rm[256], rs[256];
    int row = blockIdx.x;
    float* p = out + (size_t)row * VOCAB;
    int t = threadIdx.x;
    float m = -1e30f, s = 0.f;
    for (int i = t; i < VOCAB; i += 256) {
        float v = p[i];
        if (v > m) { s = s * __expf(m - v) + 1.f; m = v; }
        else s += __expf(v - m);
    }
    rm[t] = m; rs[t] = s; __syncthreads();
    for (int o = 128; o > 0; o >>= 1) {
        if (t < o) {
            float m2 = rm[t + o], s2 = rs[t + o];
            float M = fmaxf(rm[t], m2);
            rs[t] = rs[t] * __expf(rm[t] - M) + s2 * __expf(m2 - M);
            rm[t] = M;
        }
        __syncthreads();
    }
    float lse = rm[0] + logf(rs[0]);
    for (int i = t; i < VOCAB; i += 256) p[i] -= lse;
}

// ---------------- launch ----------------
extern "C" void kernel_launch(void* const* d_in, const int* in_sizes, int n_in,
                              void* d_out, int out_size) {
    (void)in_sizes; (void)n_in; (void)out_size;
    const float* enc   = (const float*)d_in[0];
    const int*   tgt   = (const int*)  d_in[1];
    const float* emb   = (const float*)d_in[2];
    const float* Wa_w  = (const float*)d_in[3];
    const float* Wa_b  = (const float*)d_in[4];
    const float* Ua_w  = (const float*)d_in[5];
    const float* Ua_b  = (const float*)d_in[6];
    const float* Va_w  = (const float*)d_in[7];
    const float* Va_b  = (const float*)d_in[8];
    const float* W_ih0 = (const float*)d_in[9];
    const float* W_hh0 = (const float*)d_in[10];
    const float* b_ih0 = (const float*)d_in[11];
    const float* b_hh0 = (const float*)d_in[12];
    const float* W_ih1 = (const float*)d_in[13];
    const float* W_hh1 = (const float*)d_in[14];
    const float* b_ih1 = (const float*)d_in[15];
    const float* b_hh1 = (const float*)d_in[16];
    const float* fc_w  = (const float*)d_in[17];
    const float* fc_b  = (const float*)d_in[18];

    float* out = (float*)d_out;
    float* att = out + (size_t)NB * LSEQ * VOCAB;

    static int grid_mega = 0;
    if (grid_mega == 0) {
        int dev = 0;
        cudaGetDevice(&dev);
        cudaDeviceProp prop;
        cudaGetDeviceProperties(&prop, dev);
        int perSM = 1;
        cudaOccupancyMaxActiveBlocksPerMultiprocessor(&perSM, k_mega, 256, 0);
        if (perSM < 1) perSM = 1;
        if (perSM > 2) perSM = 2;
        grid_mega = prop.multiProcessorCount * perSM;
    }

    k_init<<<256, 256>>>(Wa_b, b_hh0, b_hh1, b_ih0, b_ih1);
    k_cvtw<<<1024, 256>>>(Wa_w, W_hh0, W_hh1, W_ih0, W_ih1);
    k_cvt_fcw<<<4096, 256>>>(fc_w);
    k_uk<<<dim3(16, 64), 256>>>(enc, Ua_w, Ua_b);
    k_mega<<<grid_mega, 256>>>(enc, tgt, emb, Wa_b, Va_w, Va_b,
                               b_ih0, b_hh0, b_ih1, b_hh1, att);
    k_fc<<<dim3(VOCAB / 128, NROW / 128), 256>>>(fc_b, out);
    k_logsoftmax<<<NROW, 256>>>(out);
}